// round 8
// baseline (speedup 1.0000x reference)
#include <cuda_runtime.h>
#include <cuda_fp16.h>
#include <cstdint>

#define NN 50000
#define NE 400000
#define FULLM 0xffffffffu
#define SCAN_T 1024
#define SCAN_PER ((NN + SCAN_T - 1) / SCAN_T)   // 49

// CSR scratch. g_cnt is zeroed at module load and re-zeroed by fused_k at the
// end of every launch, so each kernel_launch/graph replay starts clean.
// g_off/g_cur are fully rewritten by scan_k, g_scol fully by scatter_k.
__device__ int g_cnt[NN];
__device__ int g_off[NN];
__device__ int g_cur[NN];
__device__ int g_scol[NE];

// ---- packed f32x2 helpers (sm_100a) ---------------------------------------
#define PACK2(d, lo, hi) \
    asm("mov.b64 %0, {%1, %2};" : "=l"(d) : "f"(lo), "f"(hi))
#define UNPACK2(lo, hi, v) \
    asm("mov.b64 {%0, %1}, %2;" : "=f"(lo), "=f"(hi) : "l"(v))
#define FMA2(d, a, b, c) \
    asm("fma.rn.f32x2 %0, %1, %2, %3;" : "=l"(d) : "l"(a), "l"(b), "l"(c))
#define CVT2(d, s) \
    asm("{\n\t.reg .b16 l,h;\n\t.reg .f32 fl,fh;\n\t" \
        "mov.b32 {l,h}, %1;\n\t" \
        "cvt.f32.f16 fl, l;\n\tcvt.f32.f16 fh, h;\n\t" \
        "mov.b64 %0, {fl,fh};\n\t}" : "=l"(d) : "r"(s))

__device__ __forceinline__ float tanh_fast(float v) {
    float y;
    asm("tanh.approx.f32 %0, %1;" : "=f"(y) : "f"(v));
    return y;
}

// ---------------------------------------------------------------------------
// Kernel 1: histogram of destination rows (also the per-node edge count).
// ---------------------------------------------------------------------------
__global__ void __launch_bounds__(256) hist_k(const int* __restrict__ ei) {
    const int stride = gridDim.x * blockDim.x;
    for (int e = blockIdx.x * blockDim.x + threadIdx.x; e < NE; e += stride)
        atomicAdd(&g_cnt[ei[e]], 1);
}

// ---------------------------------------------------------------------------
// Kernel 2: single-CTA exclusive scan of g_cnt -> g_off (and g_cur copy).
// ---------------------------------------------------------------------------
__global__ void __launch_bounds__(SCAN_T) scan_k() {
    __shared__ int wsum[32];
    const int t = threadIdx.x;
    const int lane = t & 31, wid = t >> 5;
    const int base = t * SCAN_PER;

    int s = 0;
#pragma unroll 7
    for (int i = 0; i < SCAN_PER; i++) {
        const int idx = base + i;
        if (idx < NN) s += g_cnt[idx];
    }
    // warp inclusive scan of s
    int v = s;
#pragma unroll
    for (int o = 1; o < 32; o <<= 1) {
        const int u = __shfl_up_sync(FULLM, v, o);
        if (lane >= o) v += u;
    }
    if (lane == 31) wsum[wid] = v;
    __syncthreads();
    if (wid == 0) {
        int w = wsum[lane];
#pragma unroll
        for (int o = 1; o < 32; o <<= 1) {
            const int u = __shfl_up_sync(FULLM, w, o);
            if (lane >= o) w += u;
        }
        wsum[lane] = w;
    }
    __syncthreads();
    int run = v - s + (wid ? wsum[wid - 1] : 0);   // exclusive base for thread
#pragma unroll 7
    for (int i = 0; i < SCAN_PER; i++) {
        const int idx = base + i;
        if (idx < NN) {
            g_off[idx] = run;
            g_cur[idx] = run;
            run += g_cnt[idx];
        }
    }
}

// ---------------------------------------------------------------------------
// Kernel 3: scatter cols into row-sorted order.
// ---------------------------------------------------------------------------
__global__ void __launch_bounds__(256) scatter_k(const int* __restrict__ ei) {
    const int stride = gridDim.x * blockDim.x;
    for (int e = blockIdx.x * blockDim.x + threadIdx.x; e < NE; e += stride) {
        const int r = ei[e];
        const int c = ei[NE + e];
        const int p = atomicAdd(&g_cur[r], 1);
        g_scol[p] = c;
    }
}

// ---------------------------------------------------------------------------
// Kernel 4: fused gather conv + tanh + layernorm + W_out. Warp per node.
//   - filter bank fp32->fp16 in 32KB SMEM per CTA
//     layout: [cell(64)][ipair(2)][chgrp(16)][i_in(2)][c(4)] (halves)
//   - lanes preprocess up to 32 of the node's edges in parallel
//   - dual-edge FFMA2 sweep accumulates 64ch sums in registers (4ch/lane,
//     halves A/B hold partial sums over disjoint edge subsets)
//   - cross-half merge (shfl_xor 16), then node epilogue inline
//   - resets g_cnt[n]=0 for the next launch/replay
// ---------------------------------------------------------------------------
__global__ void __launch_bounds__(256) fused_k(const float* __restrict__ x,
                                               const float* __restrict__ filters,
                                               const float* __restrict__ gamma,
                                               const float* __restrict__ beta,
                                               const float* __restrict__ W,
                                               const float* __restrict__ bo,
                                               float* __restrict__ out) {
    extern __shared__ __half sf[];  // 16384 halves = 32KB
    for (int h2 = threadIdx.x; h2 < 8192; h2 += blockDim.x) {
        const int h = h2 << 1;
        const int cell = h >> 8, rem = h & 255;
        const int ipair = rem >> 7, chgrp = (rem >> 3) & 15;
        const int i_in = (rem >> 2) & 1, c = rem & 3;
        const int i = ipair * 2 + i_in;
        const float2 v = *(const float2*)(filters + cell * 256 + i * 64 + chgrp * 4 + c);
        ((__half2*)sf)[h2] = __floats2half2_rn(v.x, v.y);
    }
    __syncthreads();

    const int lane = threadIdx.x & 31;
    const int gw = (blockIdx.x * blockDim.x + threadIdx.x) >> 5;
    const int nwarps = (gridDim.x * blockDim.x) >> 5;
    const int laneOff = (lane & 15) << 3;   // chgrp*8 halves
    const bool halfA = (lane < 16);
    const int k = lane & 15;

    for (int n = gw; n < NN; n += nwarps) {
        const float xr0 = x[n * 7 + 0];
        const float xr1 = x[n * 7 + 1];
        const float xr2 = x[n * 7 + 2];
        const int deg = g_cnt[n];
        const int base = g_off[n];

        uint64_t acc01 = 0ull, acc23 = 0ull;   // 4 channels per lane (f32x2 x2)

        for (int chunk = 0; chunk < deg; chunk += 32) {
            const int ce = chunk + lane;
            float fe0 = 0.f, fe1 = 0.f, fe2 = 0.f, fe3 = 0.f;
            float wcor[8];
            int off[8];
            bool valid = false;

            if (ce < deg) {
                const int col = g_scol[base + ce];
                const float* xc = x + col * 7;
                fe0 = xc[0]; fe1 = xc[1]; fe2 = xc[2]; fe3 = xc[6];
                const float rx = fe0 - xr0;
                const float ry = fe1 - xr1;
                const float rz = fe2 - xr2;
                const float d2 = rx * rx + ry * ry + rz * rz;
                if (d2 < 0.25f) {
                    valid = true;
                    const float t = 1.0f - 4.0f * d2;
                    const float win = t * t * t;
                    const float nrm = sqrtf(d2);
                    const float s = tanh_fast(nrm) / (nrm + 1e-8f);
                    // axis reversal: a<-z, b<-y, c<-x
                    const float a = (rz * s + 1.0f) * 1.5f;
                    const float b = (ry * s + 1.0f) * 1.5f;
                    const float c = (rx * s + 1.0f) * 1.5f;
                    const float af = floorf(a), bf = floorf(b), cf = floorf(c);
                    const int a0 = (int)af, b0 = (int)bf, c0 = (int)cf;
                    const float ad = a - af, bd = b - bf, cd = c - cf;
                    const int ia[2] = {a0, min(a0 + 1, 3)};
                    const int ib[2] = {b0, min(b0 + 1, 3)};
                    const int ic[2] = {c0, min(c0 + 1, 3)};
                    const float wa[2] = {1.0f - ad, ad};
                    const float wb[2] = {1.0f - bd, bd};
                    const float wcc[2] = {1.0f - cd, cd};
#pragma unroll
                    for (int ka = 0; ka < 2; ka++)
#pragma unroll
                        for (int kb = 0; kb < 2; kb++)
#pragma unroll
                            for (int kc = 0; kc < 2; kc++) {
                                const int kk = (ka << 2) | (kb << 1) | kc;
                                off[kk] = ((((ia[ka] << 2) + ib[kb]) << 2) + ic[kc]) << 8;
                                wcor[kk] = win * wa[ka] * wb[kb] * wcc[kc];
                            }
                }
            }

            unsigned vm = __ballot_sync(FULLM, valid);
            while (vm) {
                const int j0 = __ffs(vm) - 1;
                vm &= vm - 1;
                const bool dual = (vm != 0);
                int j1 = j0;
                if (dual) { j1 = __ffs(vm) - 1; vm &= vm - 1; }
                const int src = halfA ? j0 : j1;

                const float e0 = __shfl_sync(FULLM, fe0, src);
                const float e1 = __shfl_sync(FULLM, fe1, src);
                const float e2 = __shfl_sync(FULLM, fe2, src);
                const float e3 = __shfl_sync(FULLM, fe3, src);

                uint64_t A0 = 0ull, A1 = 0ull, A2 = 0ull, A3 = 0ull;
                uint64_t A4 = 0ull, A5 = 0ull, A6 = 0ull, A7 = 0ull;
#pragma unroll
                for (int kc = 0; kc < 8; kc++) {
                    const float wk = __shfl_sync(FULLM, wcor[kc], src);
                    const int ok = __shfl_sync(FULLM, off[kc], src);
                    uint64_t wk2; PACK2(wk2, wk, wk);
                    const __half* hp = sf + ok + laneOff;
                    const uint4 qa = *(const uint4*)(hp);        // i0,i1 x (c01,c23)
                    const uint4 qb = *(const uint4*)(hp + 128);  // i2,i3 x (c01,c23)
                    uint64_t f;
                    CVT2(f, qa.x); FMA2(A0, wk2, f, A0);
                    CVT2(f, qa.y); FMA2(A1, wk2, f, A1);
                    CVT2(f, qa.z); FMA2(A2, wk2, f, A2);
                    CVT2(f, qa.w); FMA2(A3, wk2, f, A3);
                    CVT2(f, qb.x); FMA2(A4, wk2, f, A4);
                    CVT2(f, qb.y); FMA2(A5, wk2, f, A5);
                    CVT2(f, qb.z); FMA2(A6, wk2, f, A6);
                    CVT2(f, qb.w); FMA2(A7, wk2, f, A7);
                }
                if (halfA || dual) {
                    uint64_t ev;
                    PACK2(ev, e0, e0); FMA2(acc01, ev, A0, acc01); FMA2(acc23, ev, A1, acc23);
                    PACK2(ev, e1, e1); FMA2(acc01, ev, A2, acc01); FMA2(acc23, ev, A3, acc23);
                    PACK2(ev, e2, e2); FMA2(acc01, ev, A4, acc01); FMA2(acc23, ev, A5, acc23);
                    PACK2(ev, e3, e3); FMA2(acc01, ev, A6, acc01); FMA2(acc23, ev, A7, acc23);
                }
            }
        }

        // merge half A + half B partial sums: lane & lane^16 hold same channels
        float s0, s1, s2, s3;
        UNPACK2(s0, s1, acc01);
        UNPACK2(s2, s3, acc23);
        s0 += __shfl_xor_sync(FULLM, s0, 16);
        s1 += __shfl_xor_sync(FULLM, s1, 16);
        s2 += __shfl_xor_sync(FULLM, s2, 16);
        s3 += __shfl_xor_sync(FULLM, s3, 16);

        // ---- node epilogue (per 16-lane group; halves duplicate) ----
        const float inv = 1.0f / (float)max(deg, 1);
        const float h0 = tanh_fast(s0 * inv);
        const float h1 = tanh_fast(s1 * inv);
        const float h2 = tanh_fast(s2 * inv);
        const float h3 = tanh_fast(s3 * inv);
        float evc = 0.f;
        if (k < 4) evc = (k < 3) ? x[n * 7 + k] : x[n * 7 + 6];

        if (lane == 0) g_cnt[n] = 0;   // reset for next launch (deg consumed)

        float total = h0 + h1 + h2 + h3 + evc;
#pragma unroll
        for (int o = 8; o; o >>= 1) total += __shfl_xor_sync(FULLM, total, o);
        const float mean = total * (1.0f / 68.0f);

        const float d0 = h0 - mean, d1 = h1 - mean, d2 = h2 - mean, d3 = h3 - mean;
        const float de = (k < 4) ? (evc - mean) : 0.f;
        float sq = d0 * d0 + d1 * d1 + d2 * d2 + d3 * d3 + de * de;
#pragma unroll
        for (int o = 8; o; o >>= 1) sq += __shfl_xor_sync(FULLM, sq, o);
        const float rstd = rsqrtf(sq * (1.0f / 68.0f) + 1e-5f);

        const float4 g4 = ((const float4*)(gamma + 4))[k];
        const float4 b4 = ((const float4*)(beta + 4))[k];
        const float n0 = d0 * rstd * g4.x + b4.x;
        const float n1 = d1 * rstd * g4.y + b4.y;
        const float n2 = d2 * rstd * g4.z + b4.z;
        const float n3 = d3 * rstd * g4.w + b4.w;

        const float4* Wp = (const float4*)(W + 12) + 3 * k;
        const float4 w0 = Wp[0], w1 = Wp[1], w2 = Wp[2];
        float p0 = n0 * w0.x + n1 * w0.w + n2 * w1.z + n3 * w2.y;
        float p1 = n0 * w0.y + n1 * w1.x + n2 * w1.w + n3 * w2.z;
        float p2 = n0 * w0.z + n1 * w1.y + n2 * w2.x + n3 * w2.w;
        if (k < 4) {
            const float ne = de * rstd * gamma[k] + beta[k];
            p0 += ne * W[3 * k + 0];
            p1 += ne * W[3 * k + 1];
            p2 += ne * W[3 * k + 2];
        }
#pragma unroll
        for (int o = 8; o; o >>= 1) {
            p0 += __shfl_xor_sync(FULLM, p0, o);
            p1 += __shfl_xor_sync(FULLM, p1, o);
            p2 += __shfl_xor_sync(FULLM, p2, o);
        }
        if (lane == 0) {
            out[n * 3 + 0] = p0 + bo[0];
            out[n * 3 + 1] = p1 + bo[1];
            out[n * 3 + 2] = p2 + bo[2];
        }
    }
}

// ---------------------------------------------------------------------------
extern "C" void kernel_launch(void* const* d_in, const int* in_sizes, int n_in,
                              void* d_out, int out_size) {
    const float* x       = (const float*)d_in[0];
    const int*   ei      = (const int*)d_in[1];
    const float* filters = (const float*)d_in[2];
    const float* gamma   = (const float*)d_in[3];
    const float* beta    = (const float*)d_in[4];
    const float* W       = (const float*)d_in[5];
    const float* bo      = (const float*)d_in[6];
    float* out = (float*)d_out;

    hist_k<<<400, 256>>>(ei);
    scan_k<<<1, SCAN_T>>>();
    scatter_k<<<400, 256>>>(ei);
    fused_k<<<592, 256, 32768>>>(x, filters, gamma, beta, W, bo, out);
}

// round 11
// speedup vs baseline: 2.9322x; 2.9322x over previous
#include <cuda_runtime.h>
#include <cuda_fp16.h>
#include <cstdint>

#define NN 50000
#define NE 400000
#define FULLM 0xffffffffu

// Scratch: per-node accumulator [NN,64] and edge count [NN].
// Device globals are zero-initialized at module load; node_k re-zeroes them
// after consuming, so every kernel_launch/graph replay sees zeroed scratch.
__device__ float g_sum[NN * 64];
__device__ int   g_cnt[NN];

__device__ __forceinline__ float tanh_fast(float v) {
    float y;
    asm("tanh.approx.f32 %0, %1;" : "=f"(y) : "f"(v));
    return y;
}

// ---------------------------------------------------------------------------
// Kernel 1: edge kernel.
//   - filter bank fp32->fp16 in 32KB SMEM per CTA
//     layout: [cell(64)][ipair(2)][chgrp(16)][i_in(2)][c(4)]  (halves)
//   - lane-per-edge preprocessing, ballot-compacted valid list
//   - DUAL-edge sweep: lanes 0-15 = edge A, lanes 16-31 = edge B
//   - corner loop accumulates A_i[c] = sum_k w_k F_k[i][c] in 8 __half2
//     registers via HFMA2 (no converts in the hot loop); e-vector combine
//     once per edge in fp32
//   - ALL shuffles execute warp-uniformly BEFORE any divergent branch
//   - scatter via red.global.add.v4.f32
// ---------------------------------------------------------------------------
__global__ void __launch_bounds__(256) edge_k(const float* __restrict__ x,
                                              const int* __restrict__ ei,
                                              const float* __restrict__ filters) {
    extern __shared__ __half sf[];  // 16384 halves = 32KB
    for (int h2 = threadIdx.x; h2 < 8192; h2 += blockDim.x) {
        const int h = h2 << 1;
        const int cell = h >> 8, rem = h & 255;
        const int ipair = rem >> 7, chgrp = (rem >> 3) & 15;
        const int i_in = (rem >> 2) & 1, c = rem & 3;
        const int i = ipair * 2 + i_in;
        const float2 v = *(const float2*)(filters + cell * 256 + i * 64 + chgrp * 4 + c);
        ((__half2*)sf)[h2] = __floats2half2_rn(v.x, v.y);
    }
    __syncthreads();

    const int lane = threadIdx.x & 31;
    const int gw = (blockIdx.x * blockDim.x + threadIdx.x) >> 5;
    const int nw = (gridDim.x * blockDim.x) >> 5;
    const int* __restrict__ rowp = ei;
    const int* __restrict__ colp = ei + NE;
    const int laneOff = (lane & 15) << 3;   // chgrp*8 halves
    const bool halfA = (lane < 16);

    for (int base = gw * 32; base < NE; base += nw * 32) {
        const int e = base + lane;
        int row = 0;
        float fe0 = 0.f, fe1 = 0.f, fe2 = 0.f, fe3 = 0.f;
        float wcor[8];
        int off[8];
        bool valid = false;

        if (e < NE) {
            row = rowp[e];
            const int col = colp[e];
            atomicAdd(&g_cnt[row], 1);  // count ALL edges (reference semantics)
            const float* xr = x + row * 7;
            const float* xc = x + col * 7;
            fe0 = xc[0]; fe1 = xc[1]; fe2 = xc[2]; fe3 = xc[6];
            const float rx = fe0 - xr[0];
            const float ry = fe1 - xr[1];
            const float rz = fe2 - xr[2];
            const float d2 = rx * rx + ry * ry + rz * rz;
            if (d2 < 0.25f) {
                valid = true;
                const float t = 1.0f - 4.0f * d2;
                const float win = t * t * t;
                const float nrm = sqrtf(d2);
                const float s = tanhf(nrm) / (nrm + 1e-8f);
                // axis reversal: a<-z, b<-y, c<-x
                const float a = (rz * s + 1.0f) * 1.5f;
                const float b = (ry * s + 1.0f) * 1.5f;
                const float c = (rx * s + 1.0f) * 1.5f;
                const float af = floorf(a), bf = floorf(b), cf = floorf(c);
                const int a0 = (int)af, b0 = (int)bf, c0 = (int)cf;
                const float ad = a - af, bd = b - bf, cd = c - cf;
                const int ia[2] = {a0, min(a0 + 1, 3)};
                const int ib[2] = {b0, min(b0 + 1, 3)};
                const int ic[2] = {c0, min(c0 + 1, 3)};
                const float wa[2] = {1.0f - ad, ad};
                const float wb[2] = {1.0f - bd, bd};
                const float wcc[2] = {1.0f - cd, cd};
#pragma unroll
                for (int ka = 0; ka < 2; ka++)
#pragma unroll
                    for (int kb = 0; kb < 2; kb++)
#pragma unroll
                        for (int kc = 0; kc < 2; kc++) {
                            const int k = (ka << 2) | (kb << 1) | kc;
                            off[k] = ((((ia[ka] << 2) + ib[kb]) << 2) + ic[kc]) << 8;
                            wcor[k] = win * wa[ka] * wb[kb] * wcc[kc];
                        }
            }
        }

        unsigned vm = __ballot_sync(FULLM, valid);
        while (vm) {
            const int j0 = __ffs(vm) - 1;
            vm &= vm - 1;
            const bool dual = (vm != 0);
            int j1 = j0;
            if (dual) { j1 = __ffs(vm) - 1; vm &= vm - 1; }
            const int src = halfA ? j0 : j1;

            // warp-uniform shuffles (all 32 lanes participate, no divergence)
            const int rj = __shfl_sync(FULLM, row, src);
            const float e0 = __shfl_sync(FULLM, fe0, src);
            const float e1 = __shfl_sync(FULLM, fe1, src);
            const float e2 = __shfl_sync(FULLM, fe2, src);
            const float e3 = __shfl_sync(FULLM, fe3, src);

            // A[2*i+p]: in-channel i, channel-pair p; fp16x2 accumulation
            __half2 A0 = __half2half2(__ushort_as_half(0));
            __half2 A1 = A0, A2 = A0, A3 = A0, A4 = A0, A5 = A0, A6 = A0, A7 = A0;
#pragma unroll
            for (int k = 0; k < 8; k++) {
                const float wk = __shfl_sync(FULLM, wcor[k], src);
                const int ok = __shfl_sync(FULLM, off[k], src);
                const __half2 wk2 = __float2half2_rn(wk);
                const __half* hp = sf + ok + laneOff;
                const uint4 qa = *(const uint4*)(hp);        // i0,i1 x (c01,c23)
                const uint4 qb = *(const uint4*)(hp + 128);  // i2,i3 x (c01,c23)
                A0 = __hfma2(wk2, *(const __half2*)&qa.x, A0);
                A1 = __hfma2(wk2, *(const __half2*)&qa.y, A1);
                A2 = __hfma2(wk2, *(const __half2*)&qa.z, A2);
                A3 = __hfma2(wk2, *(const __half2*)&qa.w, A3);
                A4 = __hfma2(wk2, *(const __half2*)&qb.x, A4);
                A5 = __hfma2(wk2, *(const __half2*)&qb.y, A5);
                A6 = __hfma2(wk2, *(const __half2*)&qb.z, A6);
                A7 = __hfma2(wk2, *(const __half2*)&qb.w, A7);
            }
            // combine with e-vector in fp32: acc[c] = sum_i e_i * A_i[c]
            float ax, ay, az, aw;
            float2 u;
            u = __half22float2(A0); ax = e0 * u.x;          ay = e0 * u.y;
            u = __half22float2(A1); az = e0 * u.x;          aw = e0 * u.y;
            u = __half22float2(A2); ax = fmaf(e1, u.x, ax); ay = fmaf(e1, u.y, ay);
            u = __half22float2(A3); az = fmaf(e1, u.x, az); aw = fmaf(e1, u.y, aw);
            u = __half22float2(A4); ax = fmaf(e2, u.x, ax); ay = fmaf(e2, u.y, ay);
            u = __half22float2(A5); az = fmaf(e2, u.x, az); aw = fmaf(e2, u.y, aw);
            u = __half22float2(A6); ax = fmaf(e3, u.x, ax); ay = fmaf(e3, u.y, ay);
            u = __half22float2(A7); az = fmaf(e3, u.x, az); aw = fmaf(e3, u.y, aw);

            if (halfA || dual) {
                float* dst = g_sum + (size_t)rj * 64 + ((lane & 15) << 2);
                asm volatile("red.global.add.v4.f32 [%0], {%1,%2,%3,%4};"
                             :: "l"(dst), "f"(ax), "f"(ay), "f"(az), "f"(aw)
                             : "memory");
            }
        }
    }
}

// ---------------------------------------------------------------------------
// Kernel 2: node epilogue. TWO nodes per warp (16-lane halves).
// Lane k (0-15 within half) owns conv channels 4k..4k+3 (one float4);
// lanes k<4 also own enc channel k. tanh via MUFU tanh.approx.
// Also re-zeroes g_sum/g_cnt after consuming.
// ---------------------------------------------------------------------------
__global__ void __launch_bounds__(256) node_k(const float* __restrict__ x,
                                              const float* __restrict__ gamma,
                                              const float* __restrict__ beta,
                                              const float* __restrict__ W,
                                              const float* __restrict__ bo,
                                              float* __restrict__ out) {
    const int lane = threadIdx.x & 31;
    const int half = lane >> 4;
    const int k = lane & 15;
    const int n = ((blockIdx.x * blockDim.x + threadIdx.x) >> 5) * 2 + half;
    if (n >= NN) return;

    float* s = g_sum + (size_t)n * 64;
    const float inv = 1.0f / (float)max(g_cnt[n], 1);

    const float4 hv = ((const float4*)s)[k];
    const float h0 = tanh_fast(hv.x * inv);
    const float h1 = tanh_fast(hv.y * inv);
    const float h2 = tanh_fast(hv.z * inv);
    const float h3 = tanh_fast(hv.w * inv);
    float ev = 0.f;
    if (k < 4) ev = (k < 3) ? x[n * 7 + k] : x[n * 7 + 6];

    // scratch consumed -> clean it for the next graph replay
    __syncwarp();
    ((float4*)s)[k] = make_float4(0.f, 0.f, 0.f, 0.f);
    if (k == 0) g_cnt[n] = 0;

    float total = h0 + h1 + h2 + h3 + ev;
#pragma unroll
    for (int o = 8; o; o >>= 1) total += __shfl_xor_sync(FULLM, total, o);
    const float mean = total * (1.0f / 68.0f);

    const float d0 = h0 - mean, d1 = h1 - mean, d2 = h2 - mean, d3 = h3 - mean;
    const float de = (k < 4) ? (ev - mean) : 0.f;
    float sq = d0 * d0 + d1 * d1 + d2 * d2 + d3 * d3 + de * de;
#pragma unroll
    for (int o = 8; o; o >>= 1) sq += __shfl_xor_sync(FULLM, sq, o);
    const float rstd = rsqrtf(sq * (1.0f / 68.0f) + 1e-5f);

    // conv channels: cat idx 4+4k .. 4+4k+3
    const float4 g4 = ((const float4*)(gamma + 4))[k];
    const float4 b4 = ((const float4*)(beta + 4))[k];
    const float n0 = d0 * rstd * g4.x + b4.x;
    const float n1 = d1 * rstd * g4.y + b4.y;
    const float n2 = d2 * rstd * g4.z + b4.z;
    const float n3 = d3 * rstd * g4.w + b4.w;

    // W rows 4+4k..4+4k+3 = 12 consecutive floats at W+12+12k (16B aligned)
    const float4* Wp = (const float4*)(W + 12) + 3 * k;
    const float4 w0 = Wp[0], w1 = Wp[1], w2 = Wp[2];
    float p0 = n0 * w0.x + n1 * w0.w + n2 * w1.z + n3 * w2.y;
    float p1 = n0 * w0.y + n1 * w1.x + n2 * w1.w + n3 * w2.z;
    float p2 = n0 * w0.z + n1 * w1.y + n2 * w2.x + n3 * w2.w;
    if (k < 4) {
        const float ne = de * rstd * gamma[k] + beta[k];
        p0 += ne * W[3 * k + 0];
        p1 += ne * W[3 * k + 1];
        p2 += ne * W[3 * k + 2];
    }
#pragma unroll
    for (int o = 8; o; o >>= 1) {
        p0 += __shfl_xor_sync(FULLM, p0, o);
        p1 += __shfl_xor_sync(FULLM, p1, o);
        p2 += __shfl_xor_sync(FULLM, p2, o);
    }
    if (k == 0) {
        out[n * 3 + 0] = p0 + bo[0];
        out[n * 3 + 1] = p1 + bo[1];
        out[n * 3 + 2] = p2 + bo[2];
    }
}

// ---------------------------------------------------------------------------
extern "C" void kernel_launch(void* const* d_in, const int* in_sizes, int n_in,
                              void* d_out, int out_size) {
    const float* x       = (const float*)d_in[0];
    const int*   ei      = (const int*)d_in[1];
    const float* filters = (const float*)d_in[2];
    const float* gamma   = (const float*)d_in[3];
    const float* beta    = (const float*)d_in[4];
    const float* W       = (const float*)d_in[5];
    const float* bo      = (const float*)d_in[6];
    float* out = (float*)d_out;

    edge_k<<<888, 256, 32768>>>(x, ei, filters);
    node_k<<<3125, 256>>>(x, gamma, beta, W, bo, out);  // 2 nodes/warp
}